// round 14
// baseline (speedup 1.0000x reference)
#include <cuda_runtime.h>
#include <cuda_fp16.h>
#include <cstdint>

#define CIN   128
#define KOUT  256
#define HH    56
#define WW    56
#define NIMG  32
#define HWSZ  (HH*WW)            // 3136
#define XPLANE (58*60)           // b32 units per (n,c2) plane; unit=2 fp16 ch
#define NC2   64

#define TILE_M   64
#define ROWS_CTA 2
#define NGROUP   (HH/ROWS_CTA)   // 28
#define NCHUNK   8               // chunks of 16 channels

// smem per stage (b32 units):
//  A: [tap(9)][mtile(4)][lane(32)][4] = 4608 units
//  B: [c2(8)] x (4 rows x 64 + 8 pad = 264) = 2112 units
#define A_UNITS 4608
#define B_UNITS 2112
#define STAGE_UNITS (A_UNITS + B_UNITS)      // 6720
#define STAGE_BYTES (STAGE_UNITS*4)          // 26880
#define SMEM_BYTES (2*STAGE_BYTES)           // 53760

#define GUARD 16
__device__ __align__(64) uint32_t XTH[GUARD + (size_t)NIMG*NC2*XPLANE];
__device__ uint32_t WT2[(size_t)NCHUNK*9*16*32*4];   // [chunk][tap][mt16][lane][reg]

__device__ __forceinline__ void mma_fp16(float* d, const uint32_t* a, const uint32_t* b) {
    asm volatile(
        "mma.sync.aligned.m16n8k16.row.col.f32.f16.f16.f32 "
        "{%0,%1,%2,%3}, {%4,%5,%6,%7}, {%8,%9}, {%0,%1,%2,%3};"
        : "+f"(d[0]), "+f"(d[1]), "+f"(d[2]), "+f"(d[3])
        : "r"(a[0]), "r"(a[1]), "r"(a[2]), "r"(a[3]), "r"(b[0]), "r"(b[1]));
}
__device__ __forceinline__ void cp16(uint32_t dst, const void* src) {
    asm volatile("cp.async.cg.shared.global [%0], [%1], 16;" :: "r"(dst), "l"(src));
}
__device__ __forceinline__ void lds128(uint32_t* r, uint32_t addr) {
    asm volatile("ld.shared.v4.b32 {%0,%1,%2,%3}, [%4];"
                 : "=r"(r[0]), "=r"(r[1]), "=r"(r[2]), "=r"(r[3]) : "r"(addr));
}
__device__ __forceinline__ uint32_t h2u(__half2 h) {
    return *reinterpret_cast<uint32_t*>(&h);
}

// ---------------- combined transform (vectorized; unchanged, passing) ----------------
__global__ void transform_all(const float* __restrict__ x, const float* __restrict__ k) {
    const int bid = blockIdx.x;
    const int t = threadIdx.x;
    if (bid < NIMG * NC2) {
        const int n  = bid >> 6;
        const int c2 = bid & 63;
        const float4* p0 = reinterpret_cast<const float4*>(
            x + ((size_t)(n * CIN + 2 * c2)) * HWSZ);
        const float4* p1 = p0 + (HWSZ / 4);
        uint4* dst = reinterpret_cast<uint4*>(XTH + GUARD + (size_t)bid * XPLANE);
        if (bid == 0 && t < GUARD) XTH[t] = 0u;

        const uint4 z = make_uint4(0u, 0u, 0u, 0u);
        if (t < 15) dst[t] = z;
        else if (t < 30) dst[855 + (t - 15)] = z;
        else if (t < 86) {
            const int row = t - 30 + 1;
            dst[(row * 60 + 56) >> 2] = z;
        }
        #pragma unroll
        for (int q = 0; q < 4; ++q) {
            const int idx = q * 256 + t;
            if (idx < 784) {
                const int row = idx / 14;
                const int f   = idx - row * 14;
                const float4 a = p0[idx];
                const float4 b = p1[idx];
                uint4 v;
                v.x = h2u(__floats2half2_rn(a.x, b.x));
                v.y = h2u(__floats2half2_rn(a.y, b.y));
                v.z = h2u(__floats2half2_rn(a.z, b.z));
                v.w = h2u(__floats2half2_rn(a.w, b.w));
                dst[(row + 1) * 15 + f] = v;
            }
        }
    } else {
        const int idx = (bid - NIMG * NC2) * 256 + t;   // 147456 total
        const int chunk = idx / 18432;
        int r1 = idx - chunk * 18432;
        const int tap = r1 / 2048;  r1 -= tap * 2048;
        const int mt  = r1 >> 7;
        const int ln  = (r1 >> 2) & 31;
        const int j   = r1 & 3;
        const int g   = ln >> 2, t4 = ln & 3;
        const int m   = mt * 16 + g + (j & 1) * 8;
        const int c   = chunk * 16 + 2 * t4 + (j >> 1) * 8;
        __half2 h = __floats2half2_rn(k[(size_t)(m * CIN + c) * 9 + tap],
                                      k[(size_t)(m * CIN + c + 1) * 9 + tap]);
        WT2[idx] = h2u(h);
    }
}

// ---------------- main kernel: 4 warps, warp = (M-half 32) x (1 of 2 rows) ----------------
__global__ void __launch_bounds__(128, 3)
conv_mma(const float* __restrict__ bias, float* __restrict__ out) {
    extern __shared__ uint32_t sm[];
    const int t    = threadIdx.x;
    const int wid  = t >> 5;
    const int wm   = wid >> 1;      // 0..1 : M half (32 rows)
    const int wr   = wid & 1;       // 0..1 : output row within group
    const int lane = t & 31;
    const int g    = lane >> 2;
    const int t4   = lane & 3;
    const int img  = blockIdx.y / NGROUP;
    const int grp  = blockIdx.y - img * NGROUP;
    const int oh0  = grp * ROWS_CTA;
    const int my0  = blockIdx.x * 4;
    const int m0   = blockIdx.x * TILE_M;

    uint32_t sm_u32;
    { uint64_t tmp = __cvta_generic_to_shared(sm); sm_u32 = (uint32_t)tmp; }

    float acc[2][7][4];
    #pragma unroll
    for (int mi = 0; mi < 2; ++mi)
        #pragma unroll
        for (int nj = 0; nj < 7; ++nj)
            #pragma unroll
            for (int q = 0; q < 4; ++q) acc[mi][nj][q] = 0.0f;

    const uint32_t* xg_base = XTH + GUARD + ((size_t)img * NC2) * XPLANE + (size_t)oh0 * 60;

    auto issue = [&](int chunk, int stage) {
        const uint32_t ab = sm_u32 + stage * STAGE_BYTES;
        const uint32_t bb = ab + A_UNITS * 4;
        const uint32_t* ag = WT2 + (size_t)chunk * 18432;
        // A: 1152 cp16, 9 per thread
        #pragma unroll
        for (int q = 0; q < 9; ++q) {
            const int idx = q * 128 + t;
            const int tap  = idx >> 7;
            const int rem  = idx & 127;
            const int tile = rem >> 5;
            const int ln2  = rem & 31;
            cp16(ab + idx * 16,
                 ag + (size_t)tap * 2048 + (size_t)(my0 + tile) * 128 + ln2 * 4);
        }
        // B: 512 cp16 = 8 c2 x 4 rows x 16, 4 per thread
        #pragma unroll
        for (int q = 0; q < 4; ++q) {
            const int idx = q * 128 + t;
            const int c   = idx >> 6;
            const int rem = idx & 63;
            const int row = rem >> 4;
            const int f   = rem & 15;
            cp16(bb + (c * 264 + row * 64 + f * 4) * 4,
                 xg_base + (size_t)(chunk * 8 + c) * XPLANE + row * 60 + f * 4 - 4);
        }
    };

    issue(0, 0);
    asm volatile("cp.async.commit_group;" ::: "memory");
    issue(1, 1);
    asm volatile("cp.async.commit_group;" ::: "memory");

    for (int chunk = 0; chunk < NCHUNK; ++chunk) {
        if (chunk + 1 < NCHUNK) {
            asm volatile("cp.async.wait_group 1;" ::: "memory");
        } else {
            asm volatile("cp.async.wait_group 0;" ::: "memory");
        }
        __syncthreads();

        const int stage = chunk & 1;
        const uint32_t a_base = sm_u32 + stage * STAGE_BYTES + wm * 1024 + lane * 16;
        const uint32_t* Bw = sm + stage * STAGE_UNITS + A_UNITS + t4 * 264 + wr * 64 + g;

        #pragma unroll
        for (int tap = 0; tap < 9; ++tap) {
            const int r = tap / 3;
            const int s = tap - r * 3;
            const int off = r * 64 + s + 3;

            uint32_t b[7][2];
            #pragma unroll
            for (int nj = 0; nj < 7; ++nj) {
                b[nj][0] = Bw[off + nj * 8];
                b[nj][1] = Bw[4 * 264 + off + nj * 8];
            }
            uint32_t a[2][4];
            #pragma unroll
            for (int mi = 0; mi < 2; ++mi)
                lds128(a[mi], a_base + tap * 2048 + mi * 512);

            #pragma unroll
            for (int mi = 0; mi < 2; ++mi)
                #pragma unroll
                for (int nj = 0; nj < 7; ++nj)
                    mma_fp16(acc[mi][nj], a[mi], b[nj]);
        }
        __syncthreads();

        if (chunk + 2 < NCHUNK) {
            issue(chunk + 2, stage);
            asm volatile("cp.async.commit_group;" ::: "memory");
        }
    }

    // ---- epilogue ----
    const float bv = bias[0];
    const int orow = oh0 + wr;
    #pragma unroll
    for (int mi = 0; mi < 2; ++mi) {
        const int kch = m0 + wm * 32 + mi * 16 + g;
        float* o = out + ((size_t)img * KOUT + kch) * HWSZ + (size_t)orow * WW;
        #pragma unroll
        for (int nj = 0; nj < 7; ++nj) {
            const int ow = nj * 8 + 2 * t4;
            *reinterpret_cast<float2*>(o + ow) =
                make_float2(acc[mi][nj][0] + bv, acc[mi][nj][1] + bv);
            *reinterpret_cast<float2*>(o + 8 * HWSZ + ow) =
                make_float2(acc[mi][nj][2] + bv, acc[mi][nj][3] + bv);
        }
    }
}

// ---------------- host ----------------
extern "C" void kernel_launch(void* const* d_in, const int* in_sizes, int n_in,
                              void* d_out, int out_size) {
    const float* x    = (const float*)d_in[0];
    const float* K    = (const float*)d_in[1];
    const float* bias = (const float*)d_in[2];
    float* out        = (float*)d_out;

    cudaFuncSetAttribute(conv_mma, cudaFuncAttributeMaxDynamicSharedMemorySize, SMEM_BYTES);

    transform_all<<<NIMG * NC2 + 576, 256>>>(x, K);
    dim3 grid(KOUT / TILE_M, NIMG * NGROUP);   // (4, 896) = 3584 CTAs of 128 thr
    conv_mma<<<grid, 128, SMEM_BYTES>>>(bias, out);
}

// round 15
// speedup vs baseline: 1.0363x; 1.0363x over previous
#include <cuda_runtime.h>
#include <cuda_fp16.h>
#include <cstdint>

#define CIN   128
#define KOUT  256
#define HH    56
#define WW    56
#define NIMG  32
#define HWSZ  (HH*WW)            // 3136
#define XPLANE (58*60)           // b32 units per (n,c2) plane; unit=2 fp16 ch
#define NC2   64

#define TILE_M   64
#define ROWS_CTA 4
#define NGROUP   (HH/ROWS_CTA)   // 14
#define NCHUNK   8               // chunks of 16 channels

#define NFULL    1776            // 444 groups x 4 mtiles (zero wave quantization)
#define NSMALL   64              // 16 leftover tiles split into 1-row CTAs
#define NGRID    (NFULL + NSMALL)

// smem per stage (b32 units):
//  A: [tap(9)][mtile(4)][lane(32)][4] = 4608 units
//  B full: [c2(8)] x (6 rows x 64 + 8 pad = 392) = 3136 units
//  B small: [c2(8)] x (3 rows x 64 + 8 pad = 200) = 1600 units (fits in same stage)
#define A_UNITS 4608
#define B_UNITS 3136
#define STAGE_UNITS (A_UNITS + B_UNITS)      // 7744
#define STAGE_BYTES (STAGE_UNITS*4)          // 30976
#define SMEM_BYTES (2*STAGE_BYTES)           // 61952

#define GUARD 16
__device__ __align__(64) uint32_t XTH[GUARD + (size_t)NIMG*NC2*XPLANE];
__device__ uint32_t WT2[(size_t)NCHUNK*9*16*32*4];   // [chunk][tap][mt16][lane][reg]

__device__ __forceinline__ void mma_fp16(float* d, const uint32_t* a, const uint32_t* b) {
    asm volatile(
        "mma.sync.aligned.m16n8k16.row.col.f32.f16.f16.f32 "
        "{%0,%1,%2,%3}, {%4,%5,%6,%7}, {%8,%9}, {%0,%1,%2,%3};"
        : "+f"(d[0]), "+f"(d[1]), "+f"(d[2]), "+f"(d[3])
        : "r"(a[0]), "r"(a[1]), "r"(a[2]), "r"(a[3]), "r"(b[0]), "r"(b[1]));
}
__device__ __forceinline__ void cp16(uint32_t dst, const void* src) {
    asm volatile("cp.async.cg.shared.global [%0], [%1], 16;" :: "r"(dst), "l"(src));
}
__device__ __forceinline__ void lds128(uint32_t* r, uint32_t addr) {
    asm volatile("ld.shared.v4.b32 {%0,%1,%2,%3}, [%4];"
                 : "=r"(r[0]), "=r"(r[1]), "=r"(r[2]), "=r"(r[3]) : "r"(addr));
}
__device__ __forceinline__ uint32_t h2u(__half2 h) {
    return *reinterpret_cast<uint32_t*>(&h);
}

// ---------------- combined transform (vectorized; unchanged, passing) ----------------
__global__ void transform_all(const float* __restrict__ x, const float* __restrict__ k) {
    const int bid = blockIdx.x;
    const int t = threadIdx.x;
    if (bid < NIMG * NC2) {
        const int n  = bid >> 6;
        const int c2 = bid & 63;
        const float4* p0 = reinterpret_cast<const float4*>(
            x + ((size_t)(n * CIN + 2 * c2)) * HWSZ);
        const float4* p1 = p0 + (HWSZ / 4);
        uint4* dst = reinterpret_cast<uint4*>(XTH + GUARD + (size_t)bid * XPLANE);
        if (bid == 0 && t < GUARD) XTH[t] = 0u;

        const uint4 z = make_uint4(0u, 0u, 0u, 0u);
        if (t < 15) dst[t] = z;
        else if (t < 30) dst[855 + (t - 15)] = z;
        else if (t < 86) {
            const int row = t - 30 + 1;
            dst[(row * 60 + 56) >> 2] = z;
        }
        #pragma unroll
        for (int q = 0; q < 4; ++q) {
            const int idx = q * 256 + t;
            if (idx < 784) {
                const int row = idx / 14;
                const int f   = idx - row * 14;
                const float4 a = p0[idx];
                const float4 b = p1[idx];
                uint4 v;
                v.x = h2u(__floats2half2_rn(a.x, b.x));
                v.y = h2u(__floats2half2_rn(a.y, b.y));
                v.z = h2u(__floats2half2_rn(a.z, b.z));
                v.w = h2u(__floats2half2_rn(a.w, b.w));
                dst[(row + 1) * 15 + f] = v;
            }
        }
    } else {
        const int idx = (bid - NIMG * NC2) * 256 + t;   // 147456 total
        const int chunk = idx / 18432;
        int r1 = idx - chunk * 18432;
        const int tap = r1 / 2048;  r1 -= tap * 2048;
        const int mt  = r1 >> 7;
        const int ln  = (r1 >> 2) & 31;
        const int j   = r1 & 3;
        const int g   = ln >> 2, t4 = ln & 3;
        const int m   = mt * 16 + g + (j & 1) * 8;
        const int c   = chunk * 16 + 2 * t4 + (j >> 1) * 8;
        __half2 h = __floats2half2_rn(k[(size_t)(m * CIN + c) * 9 + tap],
                                      k[(size_t)(m * CIN + c + 1) * 9 + tap]);
        WT2[idx] = h2u(h);
    }
}

// ---------------- main kernel: two-class grid ----------------
__global__ void __launch_bounds__(128, 3)
conv_mma(const float* __restrict__ bias, float* __restrict__ out) {
    extern __shared__ uint32_t sm[];
    const int t    = threadIdx.x;
    const int wid  = t >> 5;
    const int lane = t & 31;
    const int g    = lane >> 2;
    const int t4   = lane & 3;
    const int bid  = blockIdx.x;

    uint32_t sm_u32;
    { uint64_t tmp = __cvta_generic_to_shared(sm); sm_u32 = (uint32_t)tmp; }
    const float bv = bias[0];

    if (bid < NFULL) {
        // ======== FULL tile: 4 rows x M=64, warp = 1 row, full M (R13 verbatim) ========
        const int mt   = bid & 3;
        const int gid  = bid >> 2;              // 0..443
        const int img  = gid / NGROUP;
        const int grp  = gid - img * NGROUP;
        const int oh0  = grp * ROWS_CTA;
        const int my0  = mt * 4;
        const int m0   = mt * TILE_M;
        const int wn   = wid;

        float acc[4][7][4];
        #pragma unroll
        for (int mi = 0; mi < 4; ++mi)
            #pragma unroll
            for (int nj = 0; nj < 7; ++nj)
                #pragma unroll
                for (int q = 0; q < 4; ++q) acc[mi][nj][q] = 0.0f;

        const uint32_t* xg_base = XTH + GUARD + ((size_t)img * NC2) * XPLANE
                                + (size_t)oh0 * 60;

        auto issue = [&](int chunk, int stage) {
            const uint32_t ab = sm_u32 + stage * STAGE_BYTES;
            const uint32_t bb = ab + A_UNITS * 4;
            const uint32_t* ag = WT2 + (size_t)chunk * 18432;
            #pragma unroll
            for (int q = 0; q < 9; ++q) {
                const int idx = q * 128 + t;
                const int tap  = idx >> 7;
                const int rem  = idx & 127;
                const int tile = rem >> 5;
                const int ln2  = rem & 31;
                cp16(ab + idx * 16,
                     ag + (size_t)tap * 2048 + (size_t)(my0 + tile) * 128 + ln2 * 4);
            }
            #pragma unroll
            for (int q = 0; q < 6; ++q) {
                const int idx = q * 128 + t;
                const int c   = idx / 96;
                const int rem = idx - c * 96;
                const int row = rem >> 4;
                const int f   = rem & 15;
                cp16(bb + (c * 392 + row * 64 + f * 4) * 4,
                     xg_base + (size_t)(chunk * 8 + c) * XPLANE + row * 60 + f * 4 - 4);
            }
        };

        issue(0, 0);
        asm volatile("cp.async.commit_group;" ::: "memory");
        issue(1, 1);
        asm volatile("cp.async.commit_group;" ::: "memory");

        for (int chunk = 0; chunk < NCHUNK; ++chunk) {
            if (chunk + 1 < NCHUNK) {
                asm volatile("cp.async.wait_group 1;" ::: "memory");
            } else {
                asm volatile("cp.async.wait_group 0;" ::: "memory");
            }
            __syncthreads();

            const int stage = chunk & 1;
            const uint32_t a_base = sm_u32 + stage * STAGE_BYTES + lane * 16;
            const uint32_t* Bw = sm + stage * STAGE_UNITS + A_UNITS + t4 * 392
                               + wn * 64 + g;

            #pragma unroll
            for (int tap = 0; tap < 9; ++tap) {
                const int r = tap / 3;
                const int s = tap - r * 3;
                const int off = r * 64 + s + 3;

                uint32_t b[7][2];
                #pragma unroll
                for (int nj = 0; nj < 7; ++nj) {
                    b[nj][0] = Bw[off + nj * 8];
                    b[nj][1] = Bw[1568 + off + nj * 8];
                }
                uint32_t a[4][4];
                #pragma unroll
                for (int mi = 0; mi < 4; ++mi)
                    lds128(a[mi], a_base + tap * 2048 + mi * 512);

                #pragma unroll
                for (int mi = 0; mi < 4; ++mi)
                    #pragma unroll
                    for (int nj = 0; nj < 7; ++nj)
                        mma_fp16(acc[mi][nj], a[mi], b[nj]);
            }
            __syncthreads();

            if (chunk + 2 < NCHUNK) {
                issue(chunk + 2, stage);
                asm volatile("cp.async.commit_group;" ::: "memory");
            }
        }

        const int orow = oh0 + wn;
        #pragma unroll
        for (int mi = 0; mi < 4; ++mi) {
            const int kch = m0 + mi * 16 + g;
            float* o = out + ((size_t)img * KOUT + kch) * HWSZ + (size_t)orow * WW;
            #pragma unroll
            for (int nj = 0; nj < 7; ++nj) {
                const int ow = nj * 8 + 2 * t4;
                *reinterpret_cast<float2*>(o + ow) =
                    make_float2(acc[mi][nj][0] + bv, acc[mi][nj][1] + bv);
                *reinterpret_cast<float2*>(o + 8 * HWSZ + ow) =
                    make_float2(acc[mi][nj][2] + bv, acc[mi][nj][3] + bv);
            }
        }
    } else {
        // ======== SMALL tile: 1 row x M=64, warp = 16 M-rows ========
        const int sid = bid - NFULL;            // 0..63
        const int mt  = sid & 3;
        const int q2  = sid >> 2;               // 0..15
        const int rr  = q2 & 3;
        const int sg  = q2 >> 2;                // 0..3
        const int img = NIMG - 1;
        const int grp = 10 + sg;
        const int oh  = grp * ROWS_CTA + rr;    // 40..55
        const int my0 = mt * 4;
        const int m0  = mt * TILE_M;

        float acc[7][4];
        #pragma unroll
        for (int nj = 0; nj < 7; ++nj)
            #pragma unroll
            for (int q = 0; q < 4; ++q) acc[nj][q] = 0.0f;

        const uint32_t* xg_base = XTH + GUARD + ((size_t)img * NC2) * XPLANE
                                + (size_t)oh * 60;

        auto issue_s = [&](int chunk, int stage) {
            const uint32_t ab = sm_u32 + stage * STAGE_BYTES;
            const uint32_t bb = ab + A_UNITS * 4;
            const uint32_t* ag = WT2 + (size_t)chunk * 18432;
            #pragma unroll
            for (int q = 0; q < 9; ++q) {
                const int idx = q * 128 + t;
                const int tap  = idx >> 7;
                const int rem  = idx & 127;
                const int tile = rem >> 5;
                const int ln2  = rem & 31;
                cp16(ab + idx * 16,
                     ag + (size_t)tap * 2048 + (size_t)(my0 + tile) * 128 + ln2 * 4);
            }
            // B: 384 cp16 = 8 c2 x 3 rows x 16
            #pragma unroll
            for (int q = 0; q < 3; ++q) {
                const int idx = q * 128 + t;
                const int c   = idx / 48;
                const int rem = idx - c * 48;
                const int row = rem >> 4;
                const int f   = rem & 15;
                cp16(bb + (c * 200 + row * 64 + f * 4) * 4,
                     xg_base + (size_t)(chunk * 8 + c) * XPLANE + row * 60 + f * 4 - 4);
            }
        };

        issue_s(0, 0);
        asm volatile("cp.async.commit_group;" ::: "memory");
        issue_s(1, 1);
        asm volatile("cp.async.commit_group;" ::: "memory");

        for (int chunk = 0; chunk < NCHUNK; ++chunk) {
            if (chunk + 1 < NCHUNK) {
                asm volatile("cp.async.wait_group 1;" ::: "memory");
            } else {
                asm volatile("cp.async.wait_group 0;" ::: "memory");
            }
            __syncthreads();

            const int stage = chunk & 1;
            // warp wid owns mtile wid (16 M-rows)
            const uint32_t a_base = sm_u32 + stage * STAGE_BYTES + wid * 512 + lane * 16;
            const uint32_t* Bw = sm + stage * STAGE_UNITS + A_UNITS + t4 * 200 + g;

            #pragma unroll
            for (int tap = 0; tap < 9; ++tap) {
                const int r = tap / 3;
                const int s = tap - r * 3;
                const int off = r * 64 + s + 3;

                uint32_t b[7][2];
                #pragma unroll
                for (int nj = 0; nj < 7; ++nj) {
                    b[nj][0] = Bw[off + nj * 8];
                    b[nj][1] = Bw[800 + off + nj * 8];   // c2 block +4 (4*200)
                }
                uint32_t a[4];
                lds128(a, a_base + tap * 2048);

                #pragma unroll
                for (int nj = 0; nj < 7; ++nj)
                    mma_fp16(acc[nj], a, b[nj]);
            }
            __syncthreads();

            if (chunk + 2 < NCHUNK) {
                issue_s(chunk + 2, stage);
                asm volatile("cp.async.commit_group;" ::: "memory");
            }
        }

        const int kch = m0 + wid * 16 + g;
        float* o = out + ((size_t)img * KOUT + kch) * HWSZ + (size_t)oh * WW;
        #pragma unroll
        for (int nj = 0; nj < 7; ++nj) {
            const int ow = nj * 8 + 2 * t4;
            *reinterpret_cast<float2*>(o + ow) =
                make_float2(acc[nj][0] + bv, acc[nj][1] + bv);
            *reinterpret_cast<float2*>(o + 8 * HWSZ + ow) =
                make_float2(acc[nj][2] + bv, acc[nj][3] + bv);
        }
    }
}

// ---------------- host ----------------
extern "C" void kernel_launch(void* const* d_in, const int* in_sizes, int n_in,
                              void* d_out, int out_size) {
    const float* x    = (const float*)d_in[0];
    const float* K    = (const float*)d_in[1];
    const float* bias = (const float*)d_in[2];
    float* out        = (float*)d_out;

    cudaFuncSetAttribute(conv_mma, cudaFuncAttributeMaxDynamicSharedMemorySize, SMEM_BYTES);

    transform_all<<<NIMG * NC2 + 576, 256>>>(x, K);
    conv_mma<<<NGRID, 128, SMEM_BYTES>>>(bias, out);
}

// round 16
// speedup vs baseline: 1.0710x; 1.0335x over previous
#include <cuda_runtime.h>
#include <cuda_fp16.h>
#include <cstdint>

#define CIN   128
#define KOUT  256
#define HH    56
#define WW    56
#define NIMG  32
#define HWSZ  (HH*WW)            // 3136
#define XPLANE (58*60)           // b32 units per (n,c2) plane; unit=2 fp16 ch
#define NC2   64

#define TILE_M   64
#define ROWS_CTA 4
#define NGROUP   (HH/ROWS_CTA)   // 14
#define NCHUNK   8               // chunks of 16 channels

// smem per stage (b32 units):
//  A: [tap(9)][mtile(4)][lane(32)][4] = 4608 units
//  B: [c2(8)] x (6 rows x 64 + 8 pad = 392) = 3136 units
#define A_UNITS 4608
#define B_UNITS 3136
#define STAGE_UNITS (A_UNITS + B_UNITS)      // 7744
#define STAGE_BYTES (STAGE_UNITS*4)          // 30976
#define SMEM_BYTES (2*STAGE_BYTES)           // 61952

#define GUARD 16
__device__ __align__(64) uint32_t XTH[GUARD + (size_t)NIMG*NC2*XPLANE];
__device__ uint32_t WT2[(size_t)NCHUNK*9*16*32*4];   // [chunk][tap][mt16][lane][reg]

__device__ __forceinline__ void mma_fp16(float* d, const uint32_t* a, const uint32_t* b) {
    asm volatile(
        "mma.sync.aligned.m16n8k16.row.col.f32.f16.f16.f32 "
        "{%0,%1,%2,%3}, {%4,%5,%6,%7}, {%8,%9}, {%0,%1,%2,%3};"
        : "+f"(d[0]), "+f"(d[1]), "+f"(d[2]), "+f"(d[3])
        : "r"(a[0]), "r"(a[1]), "r"(a[2]), "r"(a[3]), "r"(b[0]), "r"(b[1]));
}
__device__ __forceinline__ void cp16(uint32_t dst, const void* src) {
    asm volatile("cp.async.cg.shared.global [%0], [%1], 16;" :: "r"(dst), "l"(src));
}
__device__ __forceinline__ void lds128(uint32_t* r, uint32_t addr) {
    asm volatile("ld.shared.v4.b32 {%0,%1,%2,%3}, [%4];"
                 : "=r"(r[0]), "=r"(r[1]), "=r"(r[2]), "=r"(r[3]) : "r"(addr));
}
__device__ __forceinline__ uint32_t h2u(__half2 h) {
    return *reinterpret_cast<uint32_t*>(&h);
}

// ---------------- combined transform (vectorized) ----------------
__global__ void transform_all(const float* __restrict__ x, const float* __restrict__ k) {
    const int bid = blockIdx.x;
    const int t = threadIdx.x;
    if (bid < NIMG * NC2) {
        const int n  = bid >> 6;
        const int c2 = bid & 63;
        const float4* p0 = reinterpret_cast<const float4*>(
            x + ((size_t)(n * CIN + 2 * c2)) * HWSZ);
        const float4* p1 = p0 + (HWSZ / 4);
        uint4* dst = reinterpret_cast<uint4*>(XTH + GUARD + (size_t)bid * XPLANE);
        if (bid == 0 && t < GUARD) XTH[t] = 0u;

        const uint4 z = make_uint4(0u, 0u, 0u, 0u);
        if (t < 15) dst[t] = z;
        else if (t < 30) dst[855 + (t - 15)] = z;
        else if (t < 86) {
            const int row = t - 30 + 1;
            dst[(row * 60 + 56) >> 2] = z;
        }
        #pragma unroll
        for (int q = 0; q < 4; ++q) {
            const int idx = q * 256 + t;
            if (idx < 784) {
                const int row = idx / 14;
                const int f   = idx - row * 14;
                const float4 a = p0[idx];
                const float4 b = p1[idx];
                uint4 v;
                v.x = h2u(__floats2half2_rn(a.x, b.x));
                v.y = h2u(__floats2half2_rn(a.y, b.y));
                v.z = h2u(__floats2half2_rn(a.z, b.z));
                v.w = h2u(__floats2half2_rn(a.w, b.w));
                dst[(row + 1) * 15 + f] = v;
            }
        }
    } else {
        const int idx = (bid - NIMG * NC2) * 256 + t;   // 147456 total
        const int chunk = idx / 18432;
        int r1 = idx - chunk * 18432;
        const int tap = r1 / 2048;  r1 -= tap * 2048;
        const int mt  = r1 >> 7;
        const int ln  = (r1 >> 2) & 31;
        const int j   = r1 & 3;
        const int g   = ln >> 2, t4 = ln & 3;
        const int m   = mt * 16 + g + (j & 1) * 8;
        const int c   = chunk * 16 + 2 * t4 + (j >> 1) * 8;
        __half2 h = __floats2half2_rn(k[(size_t)(m * CIN + c) * 9 + tap],
                                      k[(size_t)(m * CIN + c + 1) * 9 + tap]);
        WT2[idx] = h2u(h);
    }
}

// ---------------- main kernel: 4 warps, M=64/warp, 2-stage, 3 CTAs/SM ----------------
__global__ void __launch_bounds__(128, 3)
conv_mma(const float* __restrict__ bias, float* __restrict__ out) {
    extern __shared__ uint32_t sm[];
    const int t    = threadIdx.x;
    const int wn   = t >> 5;        // warp = output row within group
    const int lane = t & 31;
    const int g    = lane >> 2;
    const int t4   = lane & 3;
    const int img  = blockIdx.y / NGROUP;
    const int grp  = blockIdx.y - img * NGROUP;
    const int oh0  = grp * ROWS_CTA;
    const int my0  = blockIdx.x * 4;
    const int m0   = blockIdx.x * TILE_M;

    uint32_t sm_u32;
    { uint64_t tmp = __cvta_generic_to_shared(sm); sm_u32 = (uint32_t)tmp; }

    float acc[4][7][4];
    #pragma unroll
    for (int mi = 0; mi < 4; ++mi)
        #pragma unroll
        for (int nj = 0; nj < 7; ++nj)
            #pragma unroll
            for (int q = 0; q < 4; ++q) acc[mi][nj][q] = 0.0f;

    const uint32_t* xg_base = XTH + GUARD + ((size_t)img * NC2) * XPLANE + (size_t)oh0 * 60;

    auto issue = [&](int chunk, int stage) {
        const uint32_t ab = sm_u32 + stage * STAGE_BYTES;
        const uint32_t bb = ab + A_UNITS * 4;
        const uint32_t* ag = WT2 + (size_t)chunk * 18432;
        // A: 1152 cp16, 9 per thread
        #pragma unroll
        for (int q = 0; q < 9; ++q) {
            const int idx = q * 128 + t;
            const int tap  = idx >> 7;
            const int rem  = idx & 127;
            const int tile = rem >> 5;
            const int ln2  = rem & 31;
            cp16(ab + idx * 16,
                 ag + (size_t)tap * 2048 + (size_t)(my0 + tile) * 128 + ln2 * 4);
        }
        // B: 768 cp16 = 8 c2 x 6 rows x 16, 6 per thread
        #pragma unroll
        for (int q = 0; q < 6; ++q) {
            const int idx = q * 128 + t;
            const int c   = idx / 96;
            const int rem = idx - c * 96;
            const int row = rem >> 4;
            const int f   = rem & 15;
            cp16(bb + (c * 392 + row * 64 + f * 4) * 4,
                 xg_base + (size_t)(chunk * 8 + c) * XPLANE + row * 60 + f * 4 - 4);
        }
    };

    issue(0, 0);
    asm volatile("cp.async.commit_group;" ::: "memory");
    issue(1, 1);
    asm volatile("cp.async.commit_group;" ::: "memory");

    for (int chunk = 0; chunk < NCHUNK; ++chunk) {
        if (chunk + 1 < NCHUNK) {
            asm volatile("cp.async.wait_group 1;" ::: "memory");
        } else {
            asm volatile("cp.async.wait_group 0;" ::: "memory");
        }
        __syncthreads();

        const int stage = chunk & 1;
        const uint32_t a_base = sm_u32 + stage * STAGE_BYTES + lane * 16;
        const uint32_t* Bw = sm + stage * STAGE_UNITS + A_UNITS + t4 * 392 + wn * 64 + g;

        #pragma unroll
        for (int tap = 0; tap < 9; ++tap) {
            const int r = tap / 3;
            const int s = tap - r * 3;
            const int off = r * 64 + s + 3;

            uint32_t b[7][2];
            #pragma unroll
            for (int nj = 0; nj < 7; ++nj) {
                b[nj][0] = Bw[off + nj * 8];
                b[nj][1] = Bw[1568 + off + nj * 8];
            }
            uint32_t a[4][4];
            #pragma unroll
            for (int mi = 0; mi < 4; ++mi)
                lds128(a[mi], a_base + tap * 2048 + mi * 512);

            #pragma unroll
            for (int mi = 0; mi < 4; ++mi)
                #pragma unroll
                for (int nj = 0; nj < 7; ++nj)
                    mma_fp16(acc[mi][nj], a[mi], b[nj]);
        }
        __syncthreads();

        if (chunk + 2 < NCHUNK) {
            issue(chunk + 2, stage);
            asm volatile("cp.async.commit_group;" ::: "memory");
        }
    }

    // ---- epilogue ----
    const float bv = bias[0];
    const int orow = oh0 + wn;
    #pragma unroll
    for (int mi = 0; mi < 4; ++mi) {
        const int kch = m0 + mi * 16 + g;
        float* o = out + ((size_t)img * KOUT + kch) * HWSZ + (size_t)orow * WW;
        #pragma unroll
        for (int nj = 0; nj < 7; ++nj) {
            const int ow = nj * 8 + 2 * t4;
            *reinterpret_cast<float2*>(o + ow) =
                make_float2(acc[mi][nj][0] + bv, acc[mi][nj][1] + bv);
            *reinterpret_cast<float2*>(o + 8 * HWSZ + ow) =
                make_float2(acc[mi][nj][2] + bv, acc[mi][nj][3] + bv);
        }
    }
}

// ---------------- host ----------------
extern "C" void kernel_launch(void* const* d_in, const int* in_sizes, int n_in,
                              void* d_out, int out_size) {
    const float* x    = (const float*)d_in[0];
    const float* K    = (const float*)d_in[1];
    const float* bias = (const float*)d_in[2];
    float* out        = (float*)d_out;

    cudaFuncSetAttribute(conv_mma, cudaFuncAttributeMaxDynamicSharedMemorySize, SMEM_BYTES);

    transform_all<<<NIMG * NC2 + 576, 256>>>(x, K);
    dim3 grid(KOUT / TILE_M, NIMG * NGROUP);   // (4, 448) = 1792 CTAs of 128 thr
    conv_mma<<<grid, 128, SMEM_BYTES>>>(bias, out);
}